// round 6
// baseline (speedup 1.0000x reference)
#include <cuda_runtime.h>

// Problem constants
static constexpr int B = 4096;
static constexpr int K = 1024;
static constexpr int C = 10;
static constexpr int M = 19;

// Tiling: block = 16 batches (8 pairs) x 32 k-chunks = 256 threads.
// KSPLIT=2 across grid.y -> grid = 512 blocks (3.5/SM), KCHUNK=16 iters/thread.
static constexpr int NBP     = 8;               // b-pairs per block
static constexpr int NB      = 2 * NBP;         // 16 batches per block
static constexpr int NC      = 32;              // k-chunks
static constexpr int THREADS = NBP * NC;        // 256
static constexpr int KSPLIT  = 2;
static constexpr int KBLK    = K / KSPLIT;      // 512
static constexpr int KCHUNK  = KBLK / NC;       // 16

static constexpr int TPAD = 101;                // table row stride

// Cross-block scratch (zero-init at load; re-zeroed by the finishing block
// each launch -> invariant across graph replays).
__device__ float g_scratch[B * M];
__device__ int   g_ticket[B / NB];

__global__ __launch_bounds__(THREADS)
void ised_kernel(const float* __restrict__ x1,
                 const float* __restrict__ x2,
                 const int*   __restrict__ idx1,
                 const int*   __restrict__ idx2,
                 float*       __restrict__ out)
{
    __shared__ float table[NB * TPAD];           // 16 x 10x10 product tables (6.5KB)
    __shared__ float binsE[M * THREADS];         // bank-column bins, even b (19.5KB)
    __shared__ float binsO[M * THREADS];         // bank-column bins, odd b  (19.5KB)
    __shared__ float rowsum[NB][M + 1];
    __shared__ int   s_last;

    const int tid = threadIdx.x;
    const int b0  = blockIdx.x * NB;
    const int k0  = blockIdx.y * KBLK;

    // ---- Build per-b product tables ----
    for (int e = tid; e < NB * 100; e += THREADS) {
        const int bl = e / 100;
        const int ij = e - bl * 100;
        const int i  = ij / 10;
        const int j  = ij - i * 10;
        table[bl * TPAD + ij] = __ldg(&x1[(b0 + bl) * C + i]) *
                                __ldg(&x2[(b0 + bl) * C + j]);
    }
    for (int e = tid; e < M * THREADS; e += THREADS) {
        binsE[e] = 0.0f;
        binsO[e] = 0.0f;
    }
    __syncthreads();

    // ---- Main loop: int2 loads (2 adjacent b), two alias-free bin chains ----
    const int bp = tid & (NBP - 1);              // b-pair id 0..7
    const int kc = tid >> 3;                     // k-chunk id 0..31
    const int b  = b0 + bp * 2;                  // even -> 8B aligned

    const int2* __restrict__ p1 =
        (const int2*)(idx1 + (size_t)(k0 + kc * KCHUNK) * B + b);
    const int2* __restrict__ p2 =
        (const int2*)(idx2 + (size_t)(k0 + kc * KCHUNK) * B + b);

    const float* __restrict__ t0 = table + (bp * 2) * TPAD;
    const float* __restrict__ t1 = t0 + TPAD;

    #pragma unroll 8
    for (int k = 0; k < KCHUNK; k++) {
        const int2 a = __ldg(&p1[(size_t)k * (B / 2)]);
        const int2 c = __ldg(&p2[(size_t)k * (B / 2)]);
        binsE[(a.x + c.x) * THREADS + tid] += t0[a.x * 10 + c.x];
        binsO[(a.y + c.y) * THREADS + tid] += t1[a.y * 10 + c.y];
    }
    __syncthreads();

    // ---- Reduce NC partials per (b, m), push to global scratch ----
    for (int e = tid; e < NB * M; e += THREADS) {
        const int bl = e / M;
        const int m  = e - bl * M;
        const int pr = bl >> 1;
        const float* __restrict__ src = (bl & 1) ? binsO : binsE;
        float v = 0.0f;
        #pragma unroll
        for (int c2 = 0; c2 < NC; c2++) {
            v += src[m * THREADS + c2 * NBP + pr];
        }
        atomicAdd(&g_scratch[(b0 + bl) * M + m], v);
    }

    // ---- Ticket: last KSPLIT-block for this row-group does the cleanup ----
    __threadfence();
    __syncthreads();
    if (tid == 0) {
        s_last = (atomicAdd(&g_ticket[blockIdx.x], 1) == KSPLIT - 1);
    }
    __syncthreads();
    if (!s_last) return;

    // Read full sums (L2-coherent loads), stash in smem
    for (int e = tid; e < NB * M; e += THREADS) {
        const int bl = e / M;
        const int m  = e - bl * M;
        rowsum[bl][m] = __ldcg(&g_scratch[(b0 + bl) * M + m]);
    }
    __syncthreads();

    // Normalize + write out; reset scratch & ticket for next replay
    if (tid < NB) {
        float sq = 0.0f;
        #pragma unroll
        for (int m = 0; m < M; m++) {
            const float v = rowsum[tid][m];
            sq += v * v;
        }
        rowsum[tid][M] = 1.0f / fmaxf(sqrtf(sq), 1e-12f);
    }
    __syncthreads();

    for (int e = tid; e < NB * M; e += THREADS) {
        const int bl = e / M;
        const int m  = e - bl * M;
        out[(size_t)(b0 + bl) * M + m] = rowsum[bl][m] * rowsum[bl][M];
        __stcg(&g_scratch[(b0 + bl) * M + m], 0.0f);
    }
    if (tid == 0) {
        g_ticket[blockIdx.x] = 0;
    }
}

extern "C" void kernel_launch(void* const* d_in, const int* in_sizes, int n_in,
                              void* d_out, int out_size)
{
    const float* x1   = (const float*)d_in[0];   // [B, C]
    const float* x2   = (const float*)d_in[1];   // [B, C]
    const int*   idx1 = (const int*)d_in[2];     // [K, B]
    const int*   idx2 = (const int*)d_in[3];     // [K, B]
    float*       out  = (float*)d_out;           // [B, M]

    (void)in_sizes; (void)n_in; (void)out_size;

    dim3 grid(B / NB, KSPLIT);
    ised_kernel<<<grid, THREADS>>>(x1, x2, idx1, idx2, out);
}

// round 7
// speedup vs baseline: 1.6113x; 1.6113x over previous
#include <cuda_runtime.h>

// Problem constants
static constexpr int B = 4096;
static constexpr int K = 1024;
static constexpr int C = 10;
static constexpr int M = 19;

// Tiling: block = 8 batches x 64 k-chunks = 512 threads, grid = 512 blocks.
static constexpr int NB      = 8;
static constexpr int NC      = 64;
static constexpr int THREADS = NB * NC;      // 512
static constexpr int KCHUNK  = K / NC;       // 16 samples per thread
static constexpr int BT      = 4;            // load-batch depth (8 LDGs in flight)

// bins[o * BSTRIDE + tid]: bank = (o + tid) mod 32 -> conflict-free RMW
static constexpr int BSTRIDE = THREADS + 1;  // 513

__global__ __launch_bounds__(THREADS, 2)
void ised_kernel(const float* __restrict__ x1,
                 const float* __restrict__ x2,
                 const int*   __restrict__ idx1,
                 const int*   __restrict__ idx2,
                 float*       __restrict__ out)
{
    __shared__ float table[100 * NB];        // [ij][bl] bank-column (3.2KB)
    __shared__ float bins[M * BSTRIDE];      // per-thread bins, bank-column (39KB)
    __shared__ float rowsum[NB][M + 1];

    const int tid = threadIdx.x;
    const int b0  = blockIdx.x * NB;

    // ---- Build per-b product tables: table[ij*NB + bl] = x1[b,i]*x2[b,j] ----
    for (int e = tid; e < NB * 100; e += THREADS) {
        const int bl = e & (NB - 1);
        const int ij = e >> 3;              // 0..99
        const int i  = ij / 10;
        const int j  = ij - i * 10;
        table[ij * NB + bl] = __ldg(&x1[(b0 + bl) * C + i]) *
                              __ldg(&x2[(b0 + bl) * C + j]);
    }

    // ---- Zero private bins ----
    for (int e = tid; e < M * BSTRIDE; e += THREADS) {
        bins[e] = 0.0f;
    }
    __syncthreads();

    // ---- Main loop: batch BT iterations of loads, then BT bin updates ----
    const int bl = tid & (NB - 1);
    const int kc = tid >> 3;                // 0..63
    const int b  = b0 + bl;

    const int* __restrict__ p1 = idx1 + (size_t)kc * KCHUNK * B + b;
    const int* __restrict__ p2 = idx2 + (size_t)kc * KCHUNK * B + b;

    #pragma unroll
    for (int kk = 0; kk < KCHUNK; kk += BT) {
        int a1[BT], a2[BT];
        #pragma unroll
        for (int j = 0; j < BT; j++) {
            a1[j] = __ldg(&p1[(size_t)(kk + j) * B]);
            a2[j] = __ldg(&p2[(size_t)(kk + j) * B]);
        }
        #pragma unroll
        for (int j = 0; j < BT; j++) {
            const float p = table[(a1[j] * 10 + a2[j]) * NB + bl];
            bins[(a1[j] + a2[j]) * BSTRIDE + tid] += p;
        }
    }
    __syncthreads();

    // ---- Reduce NC partials per (bl, m). e -> bl fast, m slow:
    //      lanes differ in bl (and a little m) -> ~2-way bank conflicts max.
    for (int e = tid; e < NB * M; e += THREADS) {
        const int rbl = e & (NB - 1);
        const int m   = e >> 3;             // 0..18
        float v = 0.0f;
        #pragma unroll
        for (int c = 0; c < NC; c++) {
            v += bins[m * BSTRIDE + c * NB + rbl];
        }
        rowsum[rbl][m] = v;
    }
    __syncthreads();

    // ---- L2-normalize, write out ----
    if (tid < NB) {
        float sq = 0.0f;
        #pragma unroll
        for (int m = 0; m < M; m++) {
            const float v = rowsum[tid][m];
            sq += v * v;
        }
        rowsum[tid][M] = 1.0f / fmaxf(sqrtf(sq), 1e-12f);
    }
    __syncthreads();

    for (int e = tid; e < NB * M; e += THREADS) {
        const int rbl = e & (NB - 1);
        const int m   = e >> 3;
        out[(size_t)(b0 + rbl) * M + m] = rowsum[rbl][m] * rowsum[rbl][M];
    }
}

extern "C" void kernel_launch(void* const* d_in, const int* in_sizes, int n_in,
                              void* d_out, int out_size)
{
    const float* x1   = (const float*)d_in[0];   // [B, C]
    const float* x2   = (const float*)d_in[1];   // [B, C]
    const int*   idx1 = (const int*)d_in[2];     // [K, B]
    const int*   idx2 = (const int*)d_in[3];     // [K, B]
    float*       out  = (float*)d_out;           // [B, M]

    (void)in_sizes; (void)n_in; (void)out_size;

    ised_kernel<<<B / NB, THREADS>>>(x1, x2, idx1, idx2, out);
}